// round 1
// baseline (speedup 1.0000x reference)
#include <cuda_runtime.h>
#include <math.h>

#define B_DIM 8192
#define DIN   10
#define H_DIM 1900
#define H4    7600

// ---------------- device scratch (static, no allocs) ----------------
__device__ float g_sx [H4];     // gx  / ||wx col||
__device__ float g_sh [H4];     // gh  / ||wh col||
__device__ float g_smx[H_DIM];  // gmx / ||wmx col||
__device__ float g_smh[H_DIM];  // gmh / ||wmh col||
__device__ float g_xm [B_DIM * H_DIM];        //  62 MB: inputs @ wmx_n
__device__ float g_zx [B_DIM * H4];           // 249 MB: inputs @ wx_n + b
__device__ float g_m  [B_DIM * H_DIM];        //  62 MB: multiplicative state

// ---------------- helpers ----------------
__device__ __forceinline__ float sigmoidf_(float x) {
    return 1.0f / (1.0f + __expf(-x));
}

// ---------------- per-column l2 scale ----------------
__global__ void colnorm_kernel(const float* __restrict__ w, const float* __restrict__ g,
                               float* __restrict__ s, int rows, int cols) {
    int j = blockIdx.x * blockDim.x + threadIdx.x;
    if (j >= cols) return;
    float acc = 0.f;
    int i = 0;
    for (; i + 4 <= rows; i += 4) {
        float a0 = w[(size_t)(i + 0) * cols + j];
        float a1 = w[(size_t)(i + 1) * cols + j];
        float a2 = w[(size_t)(i + 2) * cols + j];
        float a3 = w[(size_t)(i + 3) * cols + j];
        acc += a0 * a0 + a1 * a1 + a2 * a2 + a3 * a3;
    }
    for (; i < rows; ++i) { float a = w[(size_t)i * cols + j]; acc += a * a; }
    s[j] = g[j] * rsqrtf(fmaxf(acc, 1e-12f));
}

// ---------------- K=10 input GEMM: out[b,j] = s[j]*sum_k x[b,k] w[k,j] (+bias[j]) ----
__global__ void input_gemm_kernel(const float* __restrict__ x, const float* __restrict__ w,
                                  const float* __restrict__ s, const float* __restrict__ bias,
                                  float* __restrict__ out, int N) {
    int idx = blockIdx.x * blockDim.x + threadIdx.x;
    int total = B_DIM * N;
    if (idx >= total) return;
    int b = idx / N;
    int j = idx - b * N;
    const float* xr = x + b * DIN;
    float acc = 0.f;
#pragma unroll
    for (int k = 0; k < DIN; ++k)
        acc += xr[k] * w[(size_t)k * N + j];
    float v = acc * s[j];
    if (bias) v += bias[j];
    out[idx] = v;
}

// ---------------- GEMM-m: m = xm ⊙ (h_prev @ (wmh * smh)) ----------------
// Block tile 128x128, K-tile 16, 256 threads, 8x8 per thread (split 4+4).
#define BM 128
#define BN 128
#define BK 16
__global__ __launch_bounds__(256)
void mstate_gemm_kernel(const float* __restrict__ A,   // h_prev [B, H]
                        const float* __restrict__ W,   // wmh    [H, H]
                        float* __restrict__ out) {     // g_m    [B, H]
    __shared__ float As[BK][BM];
    __shared__ float Bs[BK][BN];
    const int tid  = threadIdx.x;
    const int tcol = tid & 15;
    const int trow = tid >> 4;
    const int m0 = blockIdx.y * BM;
    const int n0 = blockIdx.x * BN;

    float acc[8][8];
#pragma unroll
    for (int i = 0; i < 8; ++i)
#pragma unroll
        for (int j = 0; j < 8; ++j) acc[i][j] = 0.f;

    for (int k0 = 0; k0 < H_DIM; k0 += BK) {
        // --- load A tile (float4 along K; H%4==0 so float4s are all-or-nothing valid)
#pragma unroll
        for (int i = 0; i < 2; ++i) {
            int slot = tid + i * 256;          // 512 float4 slots
            int arow = slot >> 2;
            int kk   = (slot & 3) * 4;
            float4 v = make_float4(0.f, 0.f, 0.f, 0.f);
            if (k0 + kk < H_DIM)
                v = *(const float4*)&A[(size_t)(m0 + arow) * H_DIM + k0 + kk];
            As[kk + 0][arow] = v.x; As[kk + 1][arow] = v.y;
            As[kk + 2][arow] = v.z; As[kk + 3][arow] = v.w;
        }
        // --- load B tile (scaled at load)
#pragma unroll
        for (int i = 0; i < 8; ++i) {
            int e = tid + i * 256;             // 2048 scalars
            int brow = e >> 7;
            int bcol = e & 127;
            int gk = k0 + brow, gc = n0 + bcol;
            float v = 0.f;
            if (gk < H_DIM && gc < H_DIM)
                v = W[(size_t)gk * H_DIM + gc] * g_smh[gc];
            Bs[brow][bcol] = v;
        }
        __syncthreads();
#pragma unroll
        for (int kk = 0; kk < BK; ++kk) {
            float4 a0 = *(const float4*)&As[kk][trow * 4];
            float4 a1 = *(const float4*)&As[kk][64 + trow * 4];
            float4 b0 = *(const float4*)&Bs[kk][tcol * 4];
            float4 b1 = *(const float4*)&Bs[kk][64 + tcol * 4];
            float a[8] = {a0.x, a0.y, a0.z, a0.w, a1.x, a1.y, a1.z, a1.w};
            float b[8] = {b0.x, b0.y, b0.z, b0.w, b1.x, b1.y, b1.z, b1.w};
#pragma unroll
            for (int mi = 0; mi < 8; ++mi)
#pragma unroll
                for (int ni = 0; ni < 8; ++ni)
                    acc[mi][ni] += a[mi] * b[ni];
        }
        __syncthreads();
    }
    // --- epilogue: multiply by xm
#pragma unroll
    for (int mi = 0; mi < 8; ++mi) {
        int mrow = m0 + ((mi < 4) ? trow * 4 + mi : 64 + trow * 4 + (mi - 4));
#pragma unroll
        for (int ni = 0; ni < 8; ++ni) {
            int ncol = n0 + ((ni < 4) ? tcol * 4 + ni : 64 + tcol * 4 + (ni - 4));
            if (ncol < H_DIM) {
                size_t o = (size_t)mrow * H_DIM + ncol;
                out[o] = acc[mi][ni] * g_xm[o];
            }
        }
    }
}

// ---------------- GEMM-z fused gate kernel ----------------
// Effective N per block = 128 = 32 j's x 4 gates; smem column index = (jj<<2)|gate,
// so b-fragment float4s give a thread all 4 gates of one j -> fused epilogue.
__global__ __launch_bounds__(256)
void gate_gemm_kernel(const float* __restrict__ A,      // g_m  [B, H]
                      const float* __restrict__ W,      // wh   [H, 4H]
                      const float* __restrict__ cprev,  // [B, H]
                      float* __restrict__ out_h,
                      float* __restrict__ out_c) {
    __shared__ float As[BK][BM];
    __shared__ float Bs[BK][BN];
    const int tid  = threadIdx.x;
    const int tcol = tid & 15;
    const int trow = tid >> 4;
    const int m0 = blockIdx.y * BM;
    const int j0 = blockIdx.x * 32;

    float acc[8][8];
#pragma unroll
    for (int i = 0; i < 8; ++i)
#pragma unroll
        for (int j = 0; j < 8; ++j) acc[i][j] = 0.f;

    for (int k0 = 0; k0 < H_DIM; k0 += BK) {
#pragma unroll
        for (int i = 0; i < 2; ++i) {
            int slot = tid + i * 256;
            int arow = slot >> 2;
            int kk   = (slot & 3) * 4;
            float4 v = make_float4(0.f, 0.f, 0.f, 0.f);
            if (k0 + kk < H_DIM)
                v = *(const float4*)&A[(size_t)(m0 + arow) * H_DIM + k0 + kk];
            As[kk + 0][arow] = v.x; As[kk + 1][arow] = v.y;
            As[kk + 2][arow] = v.z; As[kk + 3][arow] = v.w;
        }
#pragma unroll
        for (int i = 0; i < 8; ++i) {
            int e = tid + i * 256;
            int brow = e >> 7;
            int lc   = e & 127;            // gate-major for coalesced global reads
            int gate = lc >> 5;
            int jj   = lc & 31;
            int gk = k0 + brow;
            int j  = j0 + jj;
            float v = 0.f;
            if (gk < H_DIM && j < H_DIM) {
                int gc = gate * H_DIM + j;
                v = W[(size_t)gk * H4 + gc] * g_sh[gc];
            }
            Bs[brow][(jj << 2) | gate] = v;   // interleave gates
        }
        __syncthreads();
#pragma unroll
        for (int kk = 0; kk < BK; ++kk) {
            float4 a0 = *(const float4*)&As[kk][trow * 4];
            float4 a1 = *(const float4*)&As[kk][64 + trow * 4];
            float4 b0 = *(const float4*)&Bs[kk][tcol * 4];        // j = j0+tcol,  gates 0..3
            float4 b1 = *(const float4*)&Bs[kk][64 + tcol * 4];   // j = j0+16+tcol
            float a[8] = {a0.x, a0.y, a0.z, a0.w, a1.x, a1.y, a1.z, a1.w};
            float b[8] = {b0.x, b0.y, b0.z, b0.w, b1.x, b1.y, b1.z, b1.w};
#pragma unroll
            for (int mi = 0; mi < 8; ++mi)
#pragma unroll
                for (int ni = 0; ni < 8; ++ni)
                    acc[mi][ni] += a[mi] * b[ni];
        }
        __syncthreads();
    }
    // --- fused gate epilogue
#pragma unroll
    for (int mi = 0; mi < 8; ++mi) {
        int b = m0 + ((mi < 4) ? trow * 4 + mi : 64 + trow * 4 + (mi - 4));
#pragma unroll
        for (int half = 0; half < 2; ++half) {
            int j = j0 + tcol + half * 16;
            if (j < H_DIM) {
                size_t zb = (size_t)b * H4;
                float zi = acc[mi][half * 4 + 0] + g_zx[zb + 0 * H_DIM + j];
                float zf = acc[mi][half * 4 + 1] + g_zx[zb + 1 * H_DIM + j];
                float zo = acc[mi][half * 4 + 2] + g_zx[zb + 2 * H_DIM + j];
                float zu = acc[mi][half * 4 + 3] + g_zx[zb + 3 * H_DIM + j];
                float iv = sigmoidf_(zi);
                float fv = sigmoidf_(zf);
                float ov = sigmoidf_(zo);
                float uv = tanhf(zu);
                size_t o = (size_t)b * H_DIM + j;
                float c = fv * cprev[o] + iv * uv;
                float h = ov * tanhf(c);
                out_h[o] = h;
                out_c[o] = c;
            }
        }
    }
}

// ---------------- launch ----------------
extern "C" void kernel_launch(void* const* d_in, const int* in_sizes, int n_in,
                              void* d_out, int out_size) {
    const float* inputs = (const float*)d_in[0];
    const float* c_prev = (const float*)d_in[1];
    const float* h_prev = (const float*)d_in[2];
    const float* wx     = (const float*)d_in[3];
    const float* wh     = (const float*)d_in[4];
    const float* wmx    = (const float*)d_in[5];
    const float* wmh    = (const float*)d_in[6];
    const float* bvec   = (const float*)d_in[7];
    const float* gx     = (const float*)d_in[8];
    const float* gh     = (const float*)d_in[9];
    const float* gmx    = (const float*)d_in[10];
    const float* gmh    = (const float*)d_in[11];

    float* out   = (float*)d_out;
    float* out_h = out;
    float* out_c = out + (size_t)B_DIM * H_DIM;

    float *sx, *sh, *smx, *smh, *xm, *zx, *mbuf;
    cudaGetSymbolAddress((void**)&sx,  g_sx);
    cudaGetSymbolAddress((void**)&sh,  g_sh);
    cudaGetSymbolAddress((void**)&smx, g_smx);
    cudaGetSymbolAddress((void**)&smh, g_smh);
    cudaGetSymbolAddress((void**)&xm,  g_xm);
    cudaGetSymbolAddress((void**)&zx,  g_zx);
    cudaGetSymbolAddress((void**)&mbuf, g_m);

    // 1) per-column scales
    colnorm_kernel<<<(H4    + 255) / 256, 256>>>(wx,  gx,  sx,  DIN,   H4);
    colnorm_kernel<<<(H4    + 255) / 256, 256>>>(wh,  gh,  sh,  H_DIM, H4);
    colnorm_kernel<<<(H_DIM + 255) / 256, 256>>>(wmx, gmx, smx, DIN,   H_DIM);
    colnorm_kernel<<<(H_DIM + 255) / 256, 256>>>(wmh, gmh, smh, DIN == DIN ? H_DIM : H_DIM, H_DIM);

    // 2) K=10 input GEMMs
    input_gemm_kernel<<<(B_DIM * H_DIM + 255) / 256, 256>>>(inputs, wmx, smx, nullptr, xm, H_DIM);
    input_gemm_kernel<<<(B_DIM * H4    + 255) / 256, 256>>>(inputs, wx,  sx,  bvec,    zx, H4);

    // 3) m = xm ⊙ (h_prev @ wmh_n)
    {
        dim3 grid((H_DIM + BN - 1) / BN, B_DIM / BM);
        mstate_gemm_kernel<<<grid, 256>>>(h_prev, wmh, mbuf);
    }
    // 4) fused gate GEMM -> (h, c)
    {
        dim3 grid((H_DIM + 31) / 32, B_DIM / BM);
        gate_gemm_kernel<<<grid, 256>>>(mbuf, wh, c_prev, out_h, out_c);
    }
    (void)in_sizes; (void)n_in; (void)out_size;
}

// round 3
// speedup vs baseline: 2.2558x; 2.2558x over previous
#include <cuda_runtime.h>
#include <cuda_bf16.h>
#include <cstdint>
#include <math.h>

#define B_DIM 8192
#define DIN   10
#define H_DIM 1900
#define H4    7600
#define KP    1920          // padded K (both GEMMs)
#define NP_Z  7680          // padded N for gate GEMM
#define NP_M  1920          // padded N for m GEMM
#define NKT   30            // k-tiles of 64

// ------------------------------------------------------------------
// static device scratch (zero-initialized at load; pads never written stay 0)
// ------------------------------------------------------------------
__device__ float g_sx [H4];
__device__ float g_sh [H4];
__device__ float g_smx[H_DIM];
__device__ float g_smh[H_DIM];
__device__ float g_xm [(size_t)B_DIM * H_DIM];   // inputs @ wmx_n
__device__ float g_zx [(size_t)B_DIM * H4];      // inputs @ wx_n + b  (gate-interleaved n=j*4+g)
__device__ unsigned short g_mhi [(size_t)B_DIM * KP];
__device__ unsigned short g_mlo [(size_t)B_DIM * KP];
__device__ unsigned short g_hhi [(size_t)B_DIM * KP];
__device__ unsigned short g_hlo [(size_t)B_DIM * KP];
__device__ unsigned short g_whhi[(size_t)NP_Z * KP];
__device__ unsigned short g_whlo[(size_t)NP_Z * KP];
__device__ unsigned short g_wmhhi[(size_t)NP_M * KP];
__device__ unsigned short g_wmhlo[(size_t)NP_M * KP];

// ------------------------------------------------------------------
__device__ __forceinline__ uint32_t smem_u32(const void* p) {
    uint32_t a;
    asm("{ .reg .u64 t; cvta.to.shared.u64 t, %1; cvt.u32.u64 %0, t; }" : "=r"(a) : "l"(p));
    return a;
}
__device__ __forceinline__ void ldsm_x4(uint32_t (&r)[4], uint32_t addr) {
    asm volatile("ldmatrix.sync.aligned.m8n8.x4.shared.b16 {%0,%1,%2,%3}, [%4];"
        : "=r"(r[0]), "=r"(r[1]), "=r"(r[2]), "=r"(r[3]) : "r"(addr));
}
__device__ __forceinline__ void mma16816(float (&d)[4], const uint32_t (&a)[4],
                                         uint32_t b0, uint32_t b1) {
    asm volatile("mma.sync.aligned.m16n8k16.row.col.f32.bf16.bf16.f32 "
        "{%0,%1,%2,%3}, {%4,%5,%6,%7}, {%8,%9}, {%0,%1,%2,%3};"
        : "+f"(d[0]), "+f"(d[1]), "+f"(d[2]), "+f"(d[3])
        : "r"(a[0]), "r"(a[1]), "r"(a[2]), "r"(a[3]), "r"(b0), "r"(b1));
}
__device__ __forceinline__ float sigmoidf_(float x) { return 1.0f / (1.0f + __expf(-x)); }

// ------------------------------------------------------------------
// per-column l2 scale:  s[j] = g[j] / ||w[:,j]||
// ------------------------------------------------------------------
__global__ void colnorm_kernel(const float* __restrict__ w, const float* __restrict__ g,
                               float* __restrict__ s, int rows, int cols) {
    int j = blockIdx.x * blockDim.x + threadIdx.x;
    if (j >= cols) return;
    float acc = 0.f;
    for (int i = 0; i < rows; ++i) { float a = w[(size_t)i * cols + j]; acc += a * a; }
    s[j] = g[j] * rsqrtf(fmaxf(acc, 1e-12f));
}

// ------------------------------------------------------------------
// K=10 input GEMMs
// ------------------------------------------------------------------
__global__ void input_gemm_plain(const float* __restrict__ x, const float* __restrict__ w,
                                 const float* __restrict__ s, float* __restrict__ out) {
    long long idx = (long long)blockIdx.x * blockDim.x + threadIdx.x;
    if (idx >= (long long)B_DIM * H_DIM) return;
    int b = (int)(idx / H_DIM), j = (int)(idx - (long long)b * H_DIM);
    const float* xr = x + b * DIN;
    float acc = 0.f;
#pragma unroll
    for (int k = 0; k < DIN; ++k) acc += xr[k] * w[(size_t)k * H_DIM + j];
    out[idx] = acc * s[j];
}
// gate-interleaved zx: out[b][j*4+g] = (x @ wx_n)[b][g*1900+j] + bias
__global__ void input_gemm_gates(const float* __restrict__ x, const float* __restrict__ w,
                                 const float* __restrict__ s, const float* __restrict__ bias,
                                 float* __restrict__ out) {
    long long idx = (long long)blockIdx.x * blockDim.x + threadIdx.x;
    if (idx >= (long long)B_DIM * H4) return;
    int b = (int)(idx / H4), n = (int)(idx - (long long)b * H4);
    int j = n >> 2, g = n & 3;
    int col = g * H_DIM + j;
    const float* xr = x + b * DIN;
    float acc = 0.f;
#pragma unroll
    for (int k = 0; k < DIN; ++k) acc += xr[k] * w[(size_t)k * H4 + col];
    out[idx] = acc * s[col] + bias[col];
}

// ------------------------------------------------------------------
// fp32 -> bf16 hi/lo split with K-padding (row-major [rows, KP])
// ------------------------------------------------------------------
__global__ void split_pad_kernel(const float* __restrict__ x, unsigned short* __restrict__ hi,
                                 unsigned short* __restrict__ lo, int cols, long long total) {
    long long idx = (long long)blockIdx.x * blockDim.x + threadIdx.x;
    if (idx >= total) return;
    int c = (int)(idx % KP);
    long long r = idx / KP;
    float v = (c < cols) ? x[r * cols + c] : 0.f;
    __nv_bfloat16 h = __float2bfloat16(v);
    ((__nv_bfloat16*)hi)[idx] = h;
    ((__nv_bfloat16*)lo)[idx] = __float2bfloat16(v - __bfloat162float(h));
}

// ------------------------------------------------------------------
// transpose + scale + split:  o[n(c)][k] = w[k][c] * s[c]  (bf16 hi/lo)
// ILV=1: n = (c%1900)*4 + c/1900 (gate interleave), else n = c
// ------------------------------------------------------------------
template<int ILV>
__global__ void transp_split_kernel(const float* __restrict__ w, const float* __restrict__ s,
                                    unsigned short* __restrict__ ohi, unsigned short* __restrict__ olo,
                                    int K, int NC) {
    __shared__ float tile[32][33];
    int c0 = blockIdx.x * 32, k0 = blockIdx.y * 32;
    int tx = threadIdx.x, ty = threadIdx.y;
    int c = c0 + tx, k = k0 + ty;
    float v = 0.f;
    if (c < NC && k < K) v = w[(size_t)k * NC + c] * s[c];
    tile[ty][tx] = v;
    __syncthreads();
    c = c0 + ty; k = k0 + tx;
    if (c < NC) {
        float val = tile[tx][ty];
        int n = ILV ? ((c % H_DIM) * 4 + c / H_DIM) : c;
        __nv_bfloat16 h = __float2bfloat16(val);
        ((__nv_bfloat16*)ohi)[(size_t)n * KP + k] = h;
        ((__nv_bfloat16*)olo)[(size_t)n * KP + k] = __float2bfloat16(val - __bfloat162float(h));
    }
}

// ------------------------------------------------------------------
// mma.sync bf16-split GEMM, 128x128x64 tile, 8 warps (32x64 each),
// SW128 smem, cp.async double buffer, 3-term compensated accumulation.
// MODE 0: D = hprev@wmh_n ; write m = D*xm split to bf16 hi/lo
// MODE 1: D = m@wh_n ; fused gate epilogue -> (h, c)
// ------------------------------------------------------------------
#define TILE_B  16384
#define STAGE_B 65536
#define SMEM_T  (2 * STAGE_B)

template<int MODE>
__global__ __launch_bounds__(256, 1)
void tc_gemm_kernel(const unsigned short* __restrict__ Ahi_, const unsigned short* __restrict__ Alo_,
                    const unsigned short* __restrict__ Bhi_, const unsigned short* __restrict__ Blo_,
                    const float* __restrict__ xm, const float* __restrict__ zx,
                    const float* __restrict__ cprev,
                    float* __restrict__ outh, float* __restrict__ outc,
                    unsigned short* __restrict__ mhi, unsigned short* __restrict__ mlo) {
    extern __shared__ char smem[];
    const uint32_t sb = smem_u32(smem);
    const int tid = threadIdx.x;
    const int wid = tid >> 5, lane = tid & 31;
    const int wm = wid & 3, wn = wid >> 2;          // warp tile: rows wm*32, cols wn*64
    const int lrow = lane & 15, lseg = lane >> 4;
    const int m0 = blockIdx.y * 128, n0 = blockIdx.x * 128;

    const unsigned short* srcs[4] = {Ahi_, Alo_, Bhi_, Blo_};

    auto load_tile = [&](int st, int kt) {
        uint32_t base = sb + st * STAGE_B;
#pragma unroll
        for (int T = 0; T < 4; ++T) {
            const int rb = (T < 2) ? m0 : n0;
            const unsigned short* src = srcs[T];
#pragma unroll
            for (int i = 0; i < 4; ++i) {
                int cid = tid + i * 256;
                int row = cid >> 3, u = cid & 7;
                uint32_t so = base + T * TILE_B + row * 128 + ((u ^ (row & 7)) << 4);
                const void* gp = (const void*)(src + (size_t)(rb + row) * KP + kt * 64 + u * 8);
                asm volatile("cp.async.cg.shared.global [%0], [%1], 16;" :: "r"(so), "l"(gp));
            }
        }
        asm volatile("cp.async.commit_group;" ::: "memory");
    };

    float acc[2][8][4];
#pragma unroll
    for (int a = 0; a < 2; ++a)
#pragma unroll
        for (int b = 0; b < 8; ++b)
#pragma unroll
            for (int c = 0; c < 4; ++c) acc[a][b][c] = 0.f;

    load_tile(0, 0);

    for (int kt = 0; kt < NKT; ++kt) {
        const int cur = kt & 1;
        if (kt + 1 < NKT) {
            load_tile(cur ^ 1, kt + 1);
            asm volatile("cp.async.wait_group 1;" ::: "memory");
        } else {
            asm volatile("cp.async.wait_group 0;" ::: "memory");
        }
        __syncthreads();

        const uint32_t stb = sb + cur * STAGE_B;
#pragma unroll
        for (int ks = 0; ks < 4; ++ks) {
            uint32_t ah[2][4], al[2][4], bb[4][4];
#pragma unroll
            for (int mt = 0; mt < 2; ++mt) {
                int row = wm * 32 + mt * 16 + lrow;
                uint32_t sw = (uint32_t)(((ks * 2 + lseg) ^ (row & 7)) << 4) + (uint32_t)row * 128;
                ldsm_x4(ah[mt], stb + 0 * TILE_B + sw);
                ldsm_x4(al[mt], stb + 1 * TILE_B + sw);
            }
#pragma unroll
            for (int q = 0; q < 4; ++q) {
                int row = wn * 64 + q * 16 + lrow;
                uint32_t sw = (uint32_t)(((ks * 2 + lseg) ^ (row & 7)) << 4) + (uint32_t)row * 128;
                ldsm_x4(bb[q], stb + 2 * TILE_B + sw);
            }
#pragma unroll
            for (int mt = 0; mt < 2; ++mt)
#pragma unroll
                for (int q = 0; q < 4; ++q) {
                    mma16816(acc[mt][2 * q + 0], ah[mt], bb[q][0], bb[q][2]);
                    mma16816(acc[mt][2 * q + 1], ah[mt], bb[q][1], bb[q][3]);
                    mma16816(acc[mt][2 * q + 0], al[mt], bb[q][0], bb[q][2]);
                    mma16816(acc[mt][2 * q + 1], al[mt], bb[q][1], bb[q][3]);
                }
#pragma unroll
            for (int q = 0; q < 4; ++q) {
                int row = wn * 64 + q * 16 + lrow;
                uint32_t sw = (uint32_t)(((ks * 2 + lseg) ^ (row & 7)) << 4) + (uint32_t)row * 128;
                ldsm_x4(bb[q], stb + 3 * TILE_B + sw);
            }
#pragma unroll
            for (int mt = 0; mt < 2; ++mt)
#pragma unroll
                for (int q = 0; q < 4; ++q) {
                    mma16816(acc[mt][2 * q + 0], ah[mt], bb[q][0], bb[q][2]);
                    mma16816(acc[mt][2 * q + 1], ah[mt], bb[q][1], bb[q][3]);
                }
        }
        __syncthreads();
    }

    // ---------------- epilogue ----------------
    // fragment: c0,c1 at (row = l/4, n = 2*(l%4)+{0,1}); c2,c3 at row+8
    const int qrow = lane >> 2, qcol = lane & 3;
#pragma unroll
    for (int mt = 0; mt < 2; ++mt) {
        const int r0 = m0 + wm * 32 + mt * 16 + qrow;   // and r0+8
#pragma unroll
        for (int nt = 0; nt < 8; ++nt) {
            const int nb = n0 + wn * 64 + nt * 8;
            float c0 = acc[mt][nt][0], c1 = acc[mt][nt][1];
            float c2 = acc[mt][nt][2], c3 = acc[mt][nt][3];
            if (MODE == 0) {
                const int n = nb + 2 * qcol;
#pragma unroll
                for (int h = 0; h < 2; ++h) {
                    const int r = r0 + h * 8;
                    float v0 = (h ? c2 : c0), v1 = (h ? c3 : c1);
                    float m0v = (n + 0 < H_DIM) ? v0 * xm[(size_t)r * H_DIM + n + 0] : 0.f;
                    float m1v = (n + 1 < H_DIM) ? v1 * xm[(size_t)r * H_DIM + n + 1] : 0.f;
                    __nv_bfloat16 h0 = __float2bfloat16(m0v);
                    __nv_bfloat16 h1 = __float2bfloat16(m1v);
                    __nv_bfloat16 l0 = __float2bfloat16(m0v - __bfloat162float(h0));
                    __nv_bfloat16 l1 = __float2bfloat16(m1v - __bfloat162float(h1));
                    uint32_t hp = ((uint32_t)__bfloat16_as_ushort(h1) << 16) | __bfloat16_as_ushort(h0);
                    uint32_t lp = ((uint32_t)__bfloat16_as_ushort(l1) << 16) | __bfloat16_as_ushort(l0);
                    *(uint32_t*)(mhi + (size_t)r * KP + n) = hp;
                    *(uint32_t*)(mlo + (size_t)r * KP + n) = lp;
                }
            } else {
                // exchange within lane pair: even (l%4 in {0,2}) holds (zi,zf), odd holds (zo,zu)
                float o0 = __shfl_xor_sync(0xffffffffu, c0, 1);
                float o1 = __shfl_xor_sync(0xffffffffu, c1, 1);
                float o2 = __shfl_xor_sync(0xffffffffu, c2, 1);
                float o3 = __shfl_xor_sync(0xffffffffu, c3, 1);
                if ((qcol & 1) == 0) {
                    const int j = (nb >> 2) + (qcol >> 1);
                    if (j < H_DIM) {
                        const float4 zv0 = *(const float4*)(zx + (size_t)r0 * H4 + 4 * j);
                        const float4 zv1 = *(const float4*)(zx + (size_t)(r0 + 8) * H4 + 4 * j);
#pragma unroll
                        for (int h = 0; h < 2; ++h) {
                            const int r = r0 + h * 8;
                            const float4 zv = h ? zv1 : zv0;
                            float zi = (h ? c2 : c0) + zv.x;
                            float zf = (h ? c3 : c1) + zv.y;
                            float zo = (h ? o2 : o0) + zv.z;
                            float zu = (h ? o3 : o1) + zv.w;
                            float iv = sigmoidf_(zi), fv = sigmoidf_(zf), ov = sigmoidf_(zo);
                            float uv = tanhf(zu);
                            size_t o = (size_t)r * H_DIM + j;
                            float c = fv * cprev[o] + iv * uv;
                            outh[o] = ov * tanhf(c);
                            outc[o] = c;
                        }
                    }
                }
            }
        }
    }
}

// ------------------------------------------------------------------
// launch
// ------------------------------------------------------------------
extern "C" void kernel_launch(void* const* d_in, const int* in_sizes, int n_in,
                              void* d_out, int out_size) {
    const float* inputs = (const float*)d_in[0];
    const float* c_prev = (const float*)d_in[1];
    const float* h_prev = (const float*)d_in[2];
    const float* wx     = (const float*)d_in[3];
    const float* wh     = (const float*)d_in[4];
    const float* wmx    = (const float*)d_in[5];
    const float* wmh    = (const float*)d_in[6];
    const float* bvec   = (const float*)d_in[7];
    const float* gx     = (const float*)d_in[8];
    const float* gh     = (const float*)d_in[9];
    const float* gmx    = (const float*)d_in[10];
    const float* gmh    = (const float*)d_in[11];

    float* out_h = (float*)d_out;
    float* out_c = out_h + (size_t)B_DIM * H_DIM;

    float *sx, *sh, *smx, *smh, *xm, *zx;
    unsigned short *mhi, *mlo, *hhi, *hlo, *whhi, *whlo, *wmhhi, *wmhlo;
    cudaGetSymbolAddress((void**)&sx,   g_sx);
    cudaGetSymbolAddress((void**)&sh,   g_sh);
    cudaGetSymbolAddress((void**)&smx,  g_smx);
    cudaGetSymbolAddress((void**)&smh,  g_smh);
    cudaGetSymbolAddress((void**)&xm,   g_xm);
    cudaGetSymbolAddress((void**)&zx,   g_zx);
    cudaGetSymbolAddress((void**)&mhi,  g_mhi);
    cudaGetSymbolAddress((void**)&mlo,  g_mlo);
    cudaGetSymbolAddress((void**)&hhi,  g_hhi);
    cudaGetSymbolAddress((void**)&hlo,  g_hlo);
    cudaGetSymbolAddress((void**)&whhi, g_whhi);
    cudaGetSymbolAddress((void**)&whlo, g_whlo);
    cudaGetSymbolAddress((void**)&wmhhi, g_wmhhi);
    cudaGetSymbolAddress((void**)&wmhlo, g_wmhlo);

    cudaFuncSetAttribute(tc_gemm_kernel<0>, cudaFuncAttributeMaxDynamicSharedMemorySize, SMEM_T);
    cudaFuncSetAttribute(tc_gemm_kernel<1>, cudaFuncAttributeMaxDynamicSharedMemorySize, SMEM_T);

    // 1) per-column scales
    colnorm_kernel<<<(H4 + 255) / 256, 256>>>(wx, gx, sx, DIN, H4);
    colnorm_kernel<<<(H4 + 255) / 256, 256>>>(wh, gh, sh, H_DIM, H4);
    colnorm_kernel<<<(H_DIM + 255) / 256, 256>>>(wmx, gmx, smx, DIN, H_DIM);
    colnorm_kernel<<<(H_DIM + 255) / 256, 256>>>(wmh, gmh, smh, H_DIM, H_DIM);

    // 2) K=10 input GEMMs
    input_gemm_plain<<<(int)(((long long)B_DIM * H_DIM + 255) / 256), 256>>>(inputs, wmx, smx, xm);
    input_gemm_gates<<<(int)(((long long)B_DIM * H4 + 255) / 256), 256>>>(inputs, wx, sx, bvec, zx);

    // 3) operand conversions
    split_pad_kernel<<<(int)(((long long)B_DIM * KP + 255) / 256), 256>>>(h_prev, hhi, hlo, H_DIM, (long long)B_DIM * KP);
    {
        dim3 blk(32, 32);
        dim3 gm((H_DIM + 31) / 32, KP / 32);
        transp_split_kernel<0><<<gm, blk>>>(wmh, smh, wmhhi, wmhlo, H_DIM, H_DIM);
        dim3 gz((H4 + 31) / 32, KP / 32);
        transp_split_kernel<1><<<gz, blk>>>(wh, sh, whhi, whlo, H_DIM, H4);
    }

    // 4) GEMM-m: m = xm * (h_prev @ wmh_n) -> bf16 split
    {
        dim3 grid(NP_M / 128, B_DIM / 128);
        tc_gemm_kernel<0><<<grid, 256, SMEM_T>>>(hhi, hlo, wmhhi, wmhlo,
                                                 xm, nullptr, nullptr, nullptr, nullptr, mhi, mlo);
    }
    // 5) GEMM-z fused gates -> (h, c)
    {
        dim3 grid(NP_Z / 128, B_DIM / 128);
        tc_gemm_kernel<1><<<grid, 256, SMEM_T>>>(mhi, mlo, whhi, whlo,
                                                 nullptr, zx, c_prev, out_h, out_c, nullptr, nullptr);
    }
    (void)in_sizes; (void)n_in; (void)out_size;
}

// round 4
// speedup vs baseline: 2.4640x; 1.0923x over previous
#include <cuda_runtime.h>
#include <cuda_bf16.h>
#include <cstdint>
#include <math.h>

#define B_DIM 8192
#define DIN   10
#define H_DIM 1900
#define H4    7600
#define KP    1920          // padded K (both GEMMs)
#define NP_Z  7680          // padded N for gate GEMM
#define NP_M  1920          // padded N for m GEMM
#define KT    32            // k-tile
#define NKT   60            // k-tiles of 32

// ------------------------------------------------------------------
// static device scratch (zero-initialized at load; pads never written stay 0)
// ------------------------------------------------------------------
__device__ float g_sx [H4];
__device__ float g_sh [H4];
__device__ float g_smx[H_DIM];
__device__ float g_smh[H_DIM];
__device__ float g_xm [(size_t)B_DIM * H_DIM];   // inputs @ wmx_n
__device__ float g_zx [(size_t)B_DIM * H4];      // inputs @ wx_n + b (gate-interleaved n=j*4+g)
__device__ unsigned short g_mhi [(size_t)B_DIM * KP];
__device__ unsigned short g_mlo [(size_t)B_DIM * KP];
__device__ unsigned short g_hhi [(size_t)B_DIM * KP];
__device__ unsigned short g_hlo [(size_t)B_DIM * KP];
__device__ unsigned short g_whhi[(size_t)NP_Z * KP];
__device__ unsigned short g_whlo[(size_t)NP_Z * KP];
__device__ unsigned short g_wmhhi[(size_t)NP_M * KP];
__device__ unsigned short g_wmhlo[(size_t)NP_M * KP];

// ------------------------------------------------------------------
__device__ __forceinline__ uint32_t smem_u32(const void* p) {
    uint32_t a;
    asm("{ .reg .u64 t; cvta.to.shared.u64 t, %1; cvt.u32.u64 %0, t; }" : "=r"(a) : "l"(p));
    return a;
}
__device__ __forceinline__ void ldsm_x4(uint32_t (&r)[4], uint32_t addr) {
    asm volatile("ldmatrix.sync.aligned.m8n8.x4.shared.b16 {%0,%1,%2,%3}, [%4];"
        : "=r"(r[0]), "=r"(r[1]), "=r"(r[2]), "=r"(r[3]) : "r"(addr));
}
__device__ __forceinline__ void mma16816(float (&d)[4], const uint32_t (&a)[4],
                                         uint32_t b0, uint32_t b1) {
    asm volatile("mma.sync.aligned.m16n8k16.row.col.f32.bf16.bf16.f32 "
        "{%0,%1,%2,%3}, {%4,%5,%6,%7}, {%8,%9}, {%0,%1,%2,%3};"
        : "+f"(d[0]), "+f"(d[1]), "+f"(d[2]), "+f"(d[3])
        : "r"(a[0]), "r"(a[1]), "r"(a[2]), "r"(a[3]), "r"(b0), "r"(b1));
}
__device__ __forceinline__ float sigmoidf_(float x) { return 1.0f / (1.0f + __expf(-x)); }

// ------------------------------------------------------------------
// per-column l2 scale, parallel over rows: block = 32 cols x 8 row-lanes
// ------------------------------------------------------------------
__global__ void colnorm_kernel(const float* __restrict__ w, const float* __restrict__ g,
                               float* __restrict__ s, int rows, int cols) {
    __shared__ float red[8][33];
    const int jl = threadIdx.x & 31, rl = threadIdx.x >> 5;
    const int j = blockIdx.x * 32 + jl;
    float acc = 0.f;
    if (j < cols) {
        for (int i = rl; i < rows; i += 8) {
            float a = w[(size_t)i * cols + j];
            acc += a * a;
        }
    }
    red[rl][jl] = acc;
    __syncthreads();
    if (rl == 0 && j < cols) {
        float t = 0.f;
#pragma unroll
        for (int r = 0; r < 8; ++r) t += red[r][jl];
        s[j] = g[j] * rsqrtf(fmaxf(t, 1e-12f));
    }
}

// ------------------------------------------------------------------
// K=10 input GEMMs
// ------------------------------------------------------------------
__global__ void input_gemm_plain(const float* __restrict__ x, const float* __restrict__ w,
                                 const float* __restrict__ s, float* __restrict__ out) {
    long long idx = (long long)blockIdx.x * blockDim.x + threadIdx.x;
    if (idx >= (long long)B_DIM * H_DIM) return;
    int b = (int)(idx / H_DIM), j = (int)(idx - (long long)b * H_DIM);
    const float* xr = x + b * DIN;
    float acc = 0.f;
#pragma unroll
    for (int k = 0; k < DIN; ++k) acc += xr[k] * w[(size_t)k * H_DIM + j];
    out[idx] = acc * s[j];
}
// gate-interleaved zx: out[b][j*4+g] = (x @ wx_n)[b][g*1900+j] + bias
__global__ void input_gemm_gates(const float* __restrict__ x, const float* __restrict__ w,
                                 const float* __restrict__ s, const float* __restrict__ bias,
                                 float* __restrict__ out) {
    long long idx = (long long)blockIdx.x * blockDim.x + threadIdx.x;
    if (idx >= (long long)B_DIM * H4) return;
    int b = (int)(idx / H4), n = (int)(idx - (long long)b * H4);
    int j = n >> 2, g = n & 3;
    int col = g * H_DIM + j;
    const float* xr = x + b * DIN;
    float acc = 0.f;
#pragma unroll
    for (int k = 0; k < DIN; ++k) acc += xr[k] * w[(size_t)k * H4 + col];
    out[idx] = acc * s[col] + bias[col];
}

// ------------------------------------------------------------------
// fp32 -> bf16 hi/lo split with K-padding (row-major [rows, KP])
// ------------------------------------------------------------------
__global__ void split_pad_kernel(const float* __restrict__ x, unsigned short* __restrict__ hi,
                                 unsigned short* __restrict__ lo, int cols, long long total) {
    long long idx = (long long)blockIdx.x * blockDim.x + threadIdx.x;
    if (idx >= total) return;
    int c = (int)(idx % KP);
    long long r = idx / KP;
    float v = (c < cols) ? x[r * cols + c] : 0.f;
    __nv_bfloat16 h = __float2bfloat16(v);
    ((__nv_bfloat16*)hi)[idx] = h;
    ((__nv_bfloat16*)lo)[idx] = __float2bfloat16(v - __bfloat162float(h));
}

// ------------------------------------------------------------------
// transpose + scale + split:  o[n(c)][k] = w[k][c] * s[c]  (bf16 hi/lo)
// ILV=1: n = (c%1900)*4 + c/1900 (gate interleave), else n = c
// ------------------------------------------------------------------
template<int ILV>
__global__ void transp_split_kernel(const float* __restrict__ w, const float* __restrict__ s,
                                    unsigned short* __restrict__ ohi, unsigned short* __restrict__ olo,
                                    int K, int NC) {
    __shared__ float tile[32][33];
    int c0 = blockIdx.x * 32, k0 = blockIdx.y * 32;
    int tx = threadIdx.x, ty = threadIdx.y;
    int c = c0 + tx, k = k0 + ty;
    float v = 0.f;
    if (c < NC && k < K) v = w[(size_t)k * NC + c] * s[c];
    tile[ty][tx] = v;
    __syncthreads();
    c = c0 + ty; k = k0 + tx;
    if (c < NC) {
        float val = tile[tx][ty];
        int n = ILV ? ((c % H_DIM) * 4 + c / H_DIM) : c;
        __nv_bfloat16 h = __float2bfloat16(val);
        ((__nv_bfloat16*)ohi)[(size_t)n * KP + k] = h;
        ((__nv_bfloat16*)olo)[(size_t)n * KP + k] = __float2bfloat16(val - __bfloat162float(h));
    }
}

// ------------------------------------------------------------------
// mma.sync bf16-split GEMM, 128x128x32 tile, 8 warps (32x64 each),
// 2 stages x 32KB smem -> 2 CTAs/SM; term-major MMA ordering.
// MODE 0: D = hprev@wmh_n ; write m = D*xm split to bf16 hi/lo
// MODE 1: D = m@wh_n ; fused gate epilogue -> (h, c)
// ------------------------------------------------------------------
#define TILE_B  8192               // one operand tile: 128 x 32 x 2B
#define STAGE_B 32768
#define SMEM_T  (2 * STAGE_B)

template<int MODE>
__global__ __launch_bounds__(256, 2)
void tc_gemm_kernel(const unsigned short* __restrict__ Ahi_, const unsigned short* __restrict__ Alo_,
                    const unsigned short* __restrict__ Bhi_, const unsigned short* __restrict__ Blo_,
                    const float* __restrict__ xm, const float* __restrict__ zx,
                    const float* __restrict__ cprev,
                    float* __restrict__ outh, float* __restrict__ outc,
                    unsigned short* __restrict__ mhi, unsigned short* __restrict__ mlo) {
    extern __shared__ char smem[];
    const uint32_t sb = smem_u32(smem);
    const int tid = threadIdx.x;
    const int wid = tid >> 5, lane = tid & 31;
    const int wm = wid & 3, wn = wid >> 2;          // warp tile: rows wm*32, cols wn*64
    const int lrow = lane & 15, lseg = lane >> 4;
    const int m0 = blockIdx.y * 128, n0 = blockIdx.x * 128;

    const unsigned short* srcs[4] = {Ahi_, Alo_, Bhi_, Blo_};

    // row of KT=32 bf16 = 64 bytes = 4 x 16B units; swizzle u ^ (row&3)
    auto load_tile = [&](int st, int kt) {
        uint32_t base = sb + st * STAGE_B;
#pragma unroll
        for (int T = 0; T < 4; ++T) {
            const int rb = (T < 2) ? m0 : n0;
            const unsigned short* src = srcs[T];
#pragma unroll
            for (int i = 0; i < 2; ++i) {
                int cid = tid + i * 256;
                int row = cid >> 2, u = cid & 3;
                uint32_t so = base + T * TILE_B + row * 64 + ((u ^ (row & 3)) << 4);
                const void* gp = (const void*)(src + (size_t)(rb + row) * KP + kt * KT + u * 8);
                asm volatile("cp.async.cg.shared.global [%0], [%1], 16;" :: "r"(so), "l"(gp));
            }
        }
        asm volatile("cp.async.commit_group;" ::: "memory");
    };

    float acc[2][8][4];
#pragma unroll
    for (int a = 0; a < 2; ++a)
#pragma unroll
        for (int b = 0; b < 8; ++b)
#pragma unroll
            for (int c = 0; c < 4; ++c) acc[a][b][c] = 0.f;

    load_tile(0, 0);

    for (int kt = 0; kt < NKT; ++kt) {
        const int cur = kt & 1;
        if (kt + 1 < NKT) {
            load_tile(cur ^ 1, kt + 1);
            asm volatile("cp.async.wait_group 1;" ::: "memory");
        } else {
            asm volatile("cp.async.wait_group 0;" ::: "memory");
        }
        __syncthreads();

        const uint32_t stb = sb + cur * STAGE_B;
#pragma unroll
        for (int ks = 0; ks < 2; ++ks) {
            uint32_t ah[2][4], al[2][4], bb[4][4];
            // ---- A fragments (hi + lo)
#pragma unroll
            for (int mt = 0; mt < 2; ++mt) {
                int row = wm * 32 + mt * 16 + lrow;
                uint32_t sw = (uint32_t)(((ks * 2 + lseg) ^ (row & 3)) << 4) + (uint32_t)row * 64;
                ldsm_x4(ah[mt], stb + 0 * TILE_B + sw);
                ldsm_x4(al[mt], stb + 1 * TILE_B + sw);
            }
            // ---- B hi fragments
#pragma unroll
            for (int q = 0; q < 4; ++q) {
                int row = wn * 64 + q * 16 + lrow;
                uint32_t sw = (uint32_t)(((ks * 2 + lseg) ^ (row & 3)) << 4) + (uint32_t)row * 64;
                ldsm_x4(bb[q], stb + 2 * TILE_B + sw);
            }
            // pass 1: Ahi * Bhi  (16 independent accumulators)
#pragma unroll
            for (int mt = 0; mt < 2; ++mt)
#pragma unroll
                for (int q = 0; q < 4; ++q) {
                    mma16816(acc[mt][2 * q + 0], ah[mt], bb[q][0], bb[q][2]);
                    mma16816(acc[mt][2 * q + 1], ah[mt], bb[q][1], bb[q][3]);
                }
            // pass 2: Alo * Bhi
#pragma unroll
            for (int mt = 0; mt < 2; ++mt)
#pragma unroll
                for (int q = 0; q < 4; ++q) {
                    mma16816(acc[mt][2 * q + 0], al[mt], bb[q][0], bb[q][2]);
                    mma16816(acc[mt][2 * q + 1], al[mt], bb[q][1], bb[q][3]);
                }
            // ---- B lo fragments (reuse bb regs)
#pragma unroll
            for (int q = 0; q < 4; ++q) {
                int row = wn * 64 + q * 16 + lrow;
                uint32_t sw = (uint32_t)(((ks * 2 + lseg) ^ (row & 3)) << 4) + (uint32_t)row * 64;
                ldsm_x4(bb[q], stb + 3 * TILE_B + sw);
            }
            // pass 3: Ahi * Blo
#pragma unroll
            for (int mt = 0; mt < 2; ++mt)
#pragma unroll
                for (int q = 0; q < 4; ++q) {
                    mma16816(acc[mt][2 * q + 0], ah[mt], bb[q][0], bb[q][2]);
                    mma16816(acc[mt][2 * q + 1], ah[mt], bb[q][1], bb[q][3]);
                }
        }
        __syncthreads();
    }

    // ---------------- epilogue ----------------
    // fragment: c0,c1 at (row = l/4, n = 2*(l%4)+{0,1}); c2,c3 at row+8
    const int qrow = lane >> 2, qcol = lane & 3;
#pragma unroll
    for (int mt = 0; mt < 2; ++mt) {
        const int r0 = m0 + wm * 32 + mt * 16 + qrow;   // and r0+8
#pragma unroll
        for (int nt = 0; nt < 8; ++nt) {
            const int nb = n0 + wn * 64 + nt * 8;
            float c0 = acc[mt][nt][0], c1 = acc[mt][nt][1];
            float c2 = acc[mt][nt][2], c3 = acc[mt][nt][3];
            if (MODE == 0) {
                const int n = nb + 2 * qcol;
#pragma unroll
                for (int h = 0; h < 2; ++h) {
                    const int r = r0 + h * 8;
                    float v0 = (h ? c2 : c0), v1 = (h ? c3 : c1);
                    float m0v = (n + 0 < H_DIM) ? v0 * xm[(size_t)r * H_DIM + n + 0] : 0.f;
                    float m1v = (n + 1 < H_DIM) ? v1 * xm[(size_t)r * H_DIM + n + 1] : 0.f;
                    __nv_bfloat16 h0 = __float2bfloat16(m0v);
                    __nv_bfloat16 h1 = __float2bfloat16(m1v);
                    __nv_bfloat16 l0 = __float2bfloat16(m0v - __bfloat162float(h0));
                    __nv_bfloat16 l1 = __float2bfloat16(m1v - __bfloat162float(h1));
                    uint32_t hp = ((uint32_t)__bfloat16_as_ushort(h1) << 16) | __bfloat16_as_ushort(h0);
                    uint32_t lp = ((uint32_t)__bfloat16_as_ushort(l1) << 16) | __bfloat16_as_ushort(l0);
                    *(uint32_t*)(mhi + (size_t)r * KP + n) = hp;
                    *(uint32_t*)(mlo + (size_t)r * KP + n) = lp;
                }
            } else {
                // exchange within lane pair: even lane holds (zi,zf), odd holds (zo,zu)
                float o0 = __shfl_xor_sync(0xffffffffu, c0, 1);
                float o1 = __shfl_xor_sync(0xffffffffu, c1, 1);
                float o2 = __shfl_xor_sync(0xffffffffu, c2, 1);
                float o3 = __shfl_xor_sync(0xffffffffu, c3, 1);
                if ((qcol & 1) == 0) {
                    const int j = (nb >> 2) + (qcol >> 1);
                    if (j < H_DIM) {
                        const float4 zv0 = *(const float4*)(zx + (size_t)r0 * H4 + 4 * j);
                        const float4 zv1 = *(const float4*)(zx + (size_t)(r0 + 8) * H4 + 4 * j);
#pragma unroll
                        for (int h = 0; h < 2; ++h) {
                            const int r = r0 + h * 8;
                            const float4 zv = h ? zv1 : zv0;
                            float zi = (h ? c2 : c0) + zv.x;
                            float zf = (h ? c3 : c1) + zv.y;
                            float zo = (h ? o2 : o0) + zv.z;
                            float zu = (h ? o3 : o1) + zv.w;
                            float iv = sigmoidf_(zi), fv = sigmoidf_(zf), ov = sigmoidf_(zo);
                            float uv = tanhf(zu);
                            size_t o = (size_t)r * H_DIM + j;
                            float c = fv * cprev[o] + iv * uv;
                            outh[o] = ov * tanhf(c);
                            outc[o] = c;
                        }
                    }
                }
            }
        }
    }
}

// ------------------------------------------------------------------
// launch
// ------------------------------------------------------------------
extern "C" void kernel_launch(void* const* d_in, const int* in_sizes, int n_in,
                              void* d_out, int out_size) {
    const float* inputs = (const float*)d_in[0];
    const float* c_prev = (const float*)d_in[1];
    const float* h_prev = (const float*)d_in[2];
    const float* wx     = (const float*)d_in[3];
    const float* wh     = (const float*)d_in[4];
    const float* wmx    = (const float*)d_in[5];
    const float* wmh    = (const float*)d_in[6];
    const float* bvec   = (const float*)d_in[7];
    const float* gx     = (const float*)d_in[8];
    const float* gh     = (const float*)d_in[9];
    const float* gmx    = (const float*)d_in[10];
    const float* gmh    = (const float*)d_in[11];

    float* out_h = (float*)d_out;
    float* out_c = out_h + (size_t)B_DIM * H_DIM;

    float *sx, *sh, *smx, *smh, *xm, *zx;
    unsigned short *mhi, *mlo, *hhi, *hlo, *whhi, *whlo, *wmhhi, *wmhlo;
    cudaGetSymbolAddress((void**)&sx,   g_sx);
    cudaGetSymbolAddress((void**)&sh,   g_sh);
    cudaGetSymbolAddress((void**)&smx,  g_smx);
    cudaGetSymbolAddress((void**)&smh,  g_smh);
    cudaGetSymbolAddress((void**)&xm,   g_xm);
    cudaGetSymbolAddress((void**)&zx,   g_zx);
    cudaGetSymbolAddress((void**)&mhi,  g_mhi);
    cudaGetSymbolAddress((void**)&mlo,  g_mlo);
    cudaGetSymbolAddress((void**)&hhi,  g_hhi);
    cudaGetSymbolAddress((void**)&hlo,  g_hlo);
    cudaGetSymbolAddress((void**)&whhi, g_whhi);
    cudaGetSymbolAddress((void**)&whlo, g_whlo);
    cudaGetSymbolAddress((void**)&wmhhi, g_wmhhi);
    cudaGetSymbolAddress((void**)&wmhlo, g_wmhlo);

    cudaFuncSetAttribute(tc_gemm_kernel<0>, cudaFuncAttributeMaxDynamicSharedMemorySize, SMEM_T);
    cudaFuncSetAttribute(tc_gemm_kernel<1>, cudaFuncAttributeMaxDynamicSharedMemorySize, SMEM_T);

    // 1) per-column scales (parallel reduction)
    colnorm_kernel<<<(H4 + 31) / 32, 256>>>(wx, gx, sx, DIN, H4);
    colnorm_kernel<<<(H4 + 31) / 32, 256>>>(wh, gh, sh, H_DIM, H4);
    colnorm_kernel<<<(H_DIM + 31) / 32, 256>>>(wmx, gmx, smx, DIN, H_DIM);
    colnorm_kernel<<<(H_DIM + 31) / 32, 256>>>(wmh, gmh, smh, H_DIM, H_DIM);

    // 2) K=10 input GEMMs
    input_gemm_plain<<<(int)(((long long)B_DIM * H_DIM + 255) / 256), 256>>>(inputs, wmx, smx, xm);
    input_gemm_gates<<<(int)(((long long)B_DIM * H4 + 255) / 256), 256>>>(inputs, wx, sx, bvec, zx);

    // 3) operand conversions
    split_pad_kernel<<<(int)(((long long)B_DIM * KP + 255) / 256), 256>>>(h_prev, hhi, hlo, H_DIM, (long long)B_DIM * KP);
    {
        dim3 blk(32, 32);
        dim3 gm((H_DIM + 31) / 32, KP / 32);
        transp_split_kernel<0><<<gm, blk>>>(wmh, smh, wmhhi, wmhlo, H_DIM, H_DIM);
        dim3 gz((H4 + 31) / 32, KP / 32);
        transp_split_kernel<1><<<gz, blk>>>(wh, sh, whhi, whlo, H_DIM, H4);
    }

    // 4) GEMM-m: m = xm * (h_prev @ wmh_n) -> bf16 split
    {
        dim3 grid(NP_M / 128, B_DIM / 128);
        tc_gemm_kernel<0><<<grid, 256, SMEM_T>>>(hhi, hlo, wmhhi, wmhlo,
                                                 xm, nullptr, nullptr, nullptr, nullptr, mhi, mlo);
    }
    // 5) GEMM-z fused gates -> (h, c)
    {
        dim3 grid(NP_Z / 128, B_DIM / 128);
        tc_gemm_kernel<1><<<grid, 256, SMEM_T>>>(mhi, mlo, whhi, whlo,
                                                 nullptr, zx, c_prev, out_h, out_c, nullptr, nullptr);
    }
    (void)in_sizes; (void)n_in; (void)out_size;
}

// round 5
// speedup vs baseline: 3.0652x; 1.2440x over previous
#include <cuda_runtime.h>
#include <cuda_fp16.h>
#include <cstdint>
#include <math.h>

#define B_DIM 8192
#define DIN   10
#define H_DIM 1900
#define H4    7600
#define KP    1920          // padded K (both GEMMs)
#define NP_Z  7680          // padded N for gate GEMM
#define NP_M  1920          // padded N for m GEMM
#define KT    32            // k-tile
#define NKT   60            // k-tiles of 32

// ------------------------------------------------------------------
// static device scratch (zero-initialized at load; pads never written stay 0)
// ------------------------------------------------------------------
__device__ float g_sx [H4];
__device__ float g_sh [H4];
__device__ float g_smx[H_DIM];
__device__ float g_smh[H_DIM];
__device__ float g_xm [(size_t)B_DIM * H_DIM];   // inputs @ wmx_n
__device__ float g_zx [(size_t)B_DIM * H4];      // inputs @ wx_n + b (gate-interleaved n=j*4+g)
__device__ unsigned short g_mhi [(size_t)B_DIM * KP];   // fp16 bits
__device__ unsigned short g_mlo [(size_t)B_DIM * KP];
__device__ unsigned short g_hhi [(size_t)B_DIM * KP];
__device__ unsigned short g_hlo [(size_t)B_DIM * KP];
__device__ unsigned short g_wh16[(size_t)NP_Z * KP];    // wh_n transposed+interleaved, single fp16
__device__ unsigned short g_wmhhi[(size_t)NP_M * KP];
__device__ unsigned short g_wmhlo[(size_t)NP_M * KP];

// ------------------------------------------------------------------
__device__ __forceinline__ uint32_t smem_u32(const void* p) {
    uint32_t a;
    asm("{ .reg .u64 t; cvta.to.shared.u64 t, %1; cvt.u32.u64 %0, t; }" : "=r"(a) : "l"(p));
    return a;
}
__device__ __forceinline__ void ldsm_x4(uint32_t (&r)[4], uint32_t addr) {
    asm volatile("ldmatrix.sync.aligned.m8n8.x4.shared.b16 {%0,%1,%2,%3}, [%4];"
        : "=r"(r[0]), "=r"(r[1]), "=r"(r[2]), "=r"(r[3]) : "r"(addr));
}
__device__ __forceinline__ void mma16816(float (&d)[4], const uint32_t (&a)[4],
                                         uint32_t b0, uint32_t b1) {
    asm volatile("mma.sync.aligned.m16n8k16.row.col.f32.f16.f16.f32 "
        "{%0,%1,%2,%3}, {%4,%5,%6,%7}, {%8,%9}, {%0,%1,%2,%3};"
        : "+f"(d[0]), "+f"(d[1]), "+f"(d[2]), "+f"(d[3])
        : "r"(a[0]), "r"(a[1]), "r"(a[2]), "r"(a[3]), "r"(b0), "r"(b1));
}
__device__ __forceinline__ float sigmoidf_(float x) { return 1.0f / (1.0f + __expf(-x)); }
__device__ __forceinline__ unsigned short f2h_bits(float v) {
    return __half_as_ushort(__float2half(v));
}

// ------------------------------------------------------------------
// per-column l2 scale, parallel over rows: block = 32 cols x 8 row-lanes
// ------------------------------------------------------------------
__global__ void colnorm_kernel(const float* __restrict__ w, const float* __restrict__ g,
                               float* __restrict__ s, int rows, int cols) {
    __shared__ float red[8][33];
    const int jl = threadIdx.x & 31, rl = threadIdx.x >> 5;
    const int j = blockIdx.x * 32 + jl;
    float acc = 0.f;
    if (j < cols) {
        for (int i = rl; i < rows; i += 8) {
            float a = w[(size_t)i * cols + j];
            acc += a * a;
        }
    }
    red[rl][jl] = acc;
    __syncthreads();
    if (rl == 0 && j < cols) {
        float t = 0.f;
#pragma unroll
        for (int r = 0; r < 8; ++r) t += red[r][jl];
        s[j] = g[j] * rsqrtf(fmaxf(t, 1e-12f));
    }
}

// ------------------------------------------------------------------
// K=10 input GEMMs
// ------------------------------------------------------------------
__global__ void input_gemm_plain(const float* __restrict__ x, const float* __restrict__ w,
                                 const float* __restrict__ s, float* __restrict__ out) {
    long long idx = (long long)blockIdx.x * blockDim.x + threadIdx.x;
    if (idx >= (long long)B_DIM * H_DIM) return;
    int b = (int)(idx / H_DIM), j = (int)(idx - (long long)b * H_DIM);
    const float* xr = x + b * DIN;
    float acc = 0.f;
#pragma unroll
    for (int k = 0; k < DIN; ++k) acc += xr[k] * w[(size_t)k * H_DIM + j];
    out[idx] = acc * s[j];
}
// gate-interleaved zx: out[b][j*4+g] = (x @ wx_n)[b][g*1900+j] + bias
__global__ void input_gemm_gates(const float* __restrict__ x, const float* __restrict__ w,
                                 const float* __restrict__ s, const float* __restrict__ bias,
                                 float* __restrict__ out) {
    long long idx = (long long)blockIdx.x * blockDim.x + threadIdx.x;
    if (idx >= (long long)B_DIM * H4) return;
    int b = (int)(idx / H4), n = (int)(idx - (long long)b * H4);
    int j = n >> 2, g = n & 3;
    int col = g * H_DIM + j;
    const float* xr = x + b * DIN;
    float acc = 0.f;
#pragma unroll
    for (int k = 0; k < DIN; ++k) acc += xr[k] * w[(size_t)k * H4 + col];
    out[idx] = acc * s[col] + bias[col];
}

// ------------------------------------------------------------------
// fp32 -> fp16 hi/lo split with K-padding (row-major [rows, KP])
// ------------------------------------------------------------------
__global__ void split_pad_kernel(const float* __restrict__ x, unsigned short* __restrict__ hi,
                                 unsigned short* __restrict__ lo, int cols, long long total) {
    long long idx = (long long)blockIdx.x * blockDim.x + threadIdx.x;
    if (idx >= total) return;
    int c = (int)(idx % KP);
    long long r = idx / KP;
    float v = (c < cols) ? x[r * cols + c] : 0.f;
    __half h = __float2half(v);
    hi[idx] = __half_as_ushort(h);
    lo[idx] = f2h_bits(v - __half2float(h));
}

// ------------------------------------------------------------------
// transpose + scale (+ optional split):  o[n(c)][k] = w[k][c] * s[c]
// ILV=1: n = (c%1900)*4 + c/1900 (gate interleave), else n = c
// SPLIT=1: write hi+lo; SPLIT=0: write single fp16 (olo unused)
// ------------------------------------------------------------------
template<int ILV, int SPLIT>
__global__ void transp_split_kernel(const float* __restrict__ w, const float* __restrict__ s,
                                    unsigned short* __restrict__ ohi, unsigned short* __restrict__ olo,
                                    int K, int NC) {
    __shared__ float tile[32][33];
    int c0 = blockIdx.x * 32, k0 = blockIdx.y * 32;
    int tx = threadIdx.x, ty = threadIdx.y;
    int c = c0 + tx, k = k0 + ty;
    float v = 0.f;
    if (c < NC && k < K) v = w[(size_t)k * NC + c] * s[c];
    tile[ty][tx] = v;
    __syncthreads();
    c = c0 + ty; k = k0 + tx;
    if (c < NC) {
        float val = tile[tx][ty];
        int n = ILV ? ((c % H_DIM) * 4 + c / H_DIM) : c;
        __half h = __float2half(val);
        ohi[(size_t)n * KP + k] = __half_as_ushort(h);
        if (SPLIT) olo[(size_t)n * KP + k] = f2h_bits(val - __half2float(h));
    }
}

// ------------------------------------------------------------------
// mma.sync fp16-split GEMM, 128x128x32 tile, 8 warps (32x64 each).
// MODE 0: 3-term (Ahi,Alo,Bhi,Blo): D = hprev@wmh_n ; m = D*xm -> fp16 hi/lo
// MODE 1: 2-term (Ahi,Alo,B):       D = m@wh_n ; fused gate epilogue -> (h,c)
// ------------------------------------------------------------------
#define TILE_B  8192               // one operand tile: 128 x 32 x 2B

template<int MODE>
__global__ __launch_bounds__(256, 2)
void tc_gemm_kernel(const unsigned short* __restrict__ Ahi_, const unsigned short* __restrict__ Alo_,
                    const unsigned short* __restrict__ Bhi_, const unsigned short* __restrict__ Blo_,
                    const float* __restrict__ xm, const float* __restrict__ zx,
                    const float* __restrict__ cprev,
                    float* __restrict__ outh, float* __restrict__ outc,
                    unsigned short* __restrict__ mhi, unsigned short* __restrict__ mlo) {
    constexpr int NOPS = (MODE == 0) ? 4 : 3;
    constexpr int STAGE_B = NOPS * TILE_B;
    extern __shared__ char smem[];
    const uint32_t sb = smem_u32(smem);
    const int tid = threadIdx.x;
    const int wid = tid >> 5, lane = tid & 31;
    const int wm = wid & 3, wn = wid >> 2;          // warp tile: rows wm*32, cols wn*64
    const int lrow = lane & 15, lseg = lane >> 4;
    const int m0 = blockIdx.y * 128, n0 = blockIdx.x * 128;

    const unsigned short* srcs[4] = {Ahi_, Alo_, Bhi_, Blo_};

    // row of KT=32 fp16 = 64 bytes = 4 x 16B units; swizzle u ^ (row&3)
    auto load_tile = [&](int st, int kt) {
        uint32_t base = sb + st * STAGE_B;
#pragma unroll
        for (int T = 0; T < NOPS; ++T) {
            const int rb = (T < 2) ? m0 : n0;
            const unsigned short* src = srcs[T];
#pragma unroll
            for (int i = 0; i < 2; ++i) {
                int cid = tid + i * 256;
                int row = cid >> 2, u = cid & 3;
                uint32_t so = base + T * TILE_B + row * 64 + ((u ^ (row & 3)) << 4);
                const void* gp = (const void*)(src + (size_t)(rb + row) * KP + kt * KT + u * 8);
                asm volatile("cp.async.cg.shared.global [%0], [%1], 16;" :: "r"(so), "l"(gp));
            }
        }
        asm volatile("cp.async.commit_group;" ::: "memory");
    };

    float acc[2][8][4];
#pragma unroll
    for (int a = 0; a < 2; ++a)
#pragma unroll
        for (int b = 0; b < 8; ++b)
#pragma unroll
            for (int c = 0; c < 4; ++c) acc[a][b][c] = 0.f;

    load_tile(0, 0);

    for (int kt = 0; kt < NKT; ++kt) {
        const int cur = kt & 1;
        if (kt + 1 < NKT) {
            load_tile(cur ^ 1, kt + 1);
            asm volatile("cp.async.wait_group 1;" ::: "memory");
        } else {
            asm volatile("cp.async.wait_group 0;" ::: "memory");
        }
        __syncthreads();

        const uint32_t stb = sb + cur * STAGE_B;
#pragma unroll
        for (int ks = 0; ks < 2; ++ks) {
            uint32_t ah[2][4], al[2][4], bb[4][4];
#pragma unroll
            for (int mt = 0; mt < 2; ++mt) {
                int row = wm * 32 + mt * 16 + lrow;
                uint32_t sw = (uint32_t)(((ks * 2 + lseg) ^ (row & 3)) << 4) + (uint32_t)row * 64;
                ldsm_x4(ah[mt], stb + 0 * TILE_B + sw);
                ldsm_x4(al[mt], stb + 1 * TILE_B + sw);
            }
#pragma unroll
            for (int q = 0; q < 4; ++q) {
                int row = wn * 64 + q * 16 + lrow;
                uint32_t sw = (uint32_t)(((ks * 2 + lseg) ^ (row & 3)) << 4) + (uint32_t)row * 64;
                ldsm_x4(bb[q], stb + 2 * TILE_B + sw);
            }
            // pass 1: Ahi * Bhi
#pragma unroll
            for (int mt = 0; mt < 2; ++mt)
#pragma unroll
                for (int q = 0; q < 4; ++q) {
                    mma16816(acc[mt][2 * q + 0], ah[mt], bb[q][0], bb[q][2]);
                    mma16816(acc[mt][2 * q + 1], ah[mt], bb[q][1], bb[q][3]);
                }
            // pass 2: Alo * Bhi
#pragma unroll
            for (int mt = 0; mt < 2; ++mt)
#pragma unroll
                for (int q = 0; q < 4; ++q) {
                    mma16816(acc[mt][2 * q + 0], al[mt], bb[q][0], bb[q][2]);
                    mma16816(acc[mt][2 * q + 1], al[mt], bb[q][1], bb[q][3]);
                }
            if (MODE == 0) {
                // pass 3: Ahi * Blo
#pragma unroll
                for (int q = 0; q < 4; ++q) {
                    int row = wn * 64 + q * 16 + lrow;
                    uint32_t sw = (uint32_t)(((ks * 2 + lseg) ^ (row & 3)) << 4) + (uint32_t)row * 64;
                    ldsm_x4(bb[q], stb + 3 * TILE_B + sw);
                }
#pragma unroll
                for (int mt = 0; mt < 2; ++mt)
#pragma unroll
                    for (int q = 0; q < 4; ++q) {
                        mma16816(acc[mt][2 * q + 0], ah[mt], bb[q][0], bb[q][2]);
                        mma16816(acc[mt][2 * q + 1], ah[mt], bb[q][1], bb[q][3]);
                    }
            }
        }
        __syncthreads();
    }

    // ---------------- epilogue ----------------
    // fragment: c0,c1 at (row = l/4, n = 2*(l%4)+{0,1}); c2,c3 at row+8
    const int qrow = lane >> 2, qcol = lane & 3;
#pragma unroll
    for (int mt = 0; mt < 2; ++mt) {
        const int r0 = m0 + wm * 32 + mt * 16 + qrow;   // and r0+8
#pragma unroll
        for (int nt = 0; nt < 8; ++nt) {
            const int nb = n0 + wn * 64 + nt * 8;
            float c0 = acc[mt][nt][0], c1 = acc[mt][nt][1];
            float c2 = acc[mt][nt][2], c3 = acc[mt][nt][3];
            if (MODE == 0) {
                const int n = nb + 2 * qcol;
#pragma unroll
                for (int h = 0; h < 2; ++h) {
                    const int r = r0 + h * 8;
                    float v0 = (h ? c2 : c0), v1 = (h ? c3 : c1);
                    float m0v = (n + 0 < H_DIM) ? v0 * xm[(size_t)r * H_DIM + n + 0] : 0.f;
                    float m1v = (n + 1 < H_DIM) ? v1 * xm[(size_t)r * H_DIM + n + 1] : 0.f;
                    __half h0 = __float2half(m0v);
                    __half h1 = __float2half(m1v);
                    unsigned short l0 = f2h_bits(m0v - __half2float(h0));
                    unsigned short l1 = f2h_bits(m1v - __half2float(h1));
                    uint32_t hp = ((uint32_t)__half_as_ushort(h1) << 16) | __half_as_ushort(h0);
                    uint32_t lp = ((uint32_t)l1 << 16) | l0;
                    *(uint32_t*)(mhi + (size_t)r * KP + n) = hp;
                    *(uint32_t*)(mlo + (size_t)r * KP + n) = lp;
                }
            } else {
                // exchange within lane pair: even lane holds (zi,zf), odd holds (zo,zu)
                float o0 = __shfl_xor_sync(0xffffffffu, c0, 1);
                float o1 = __shfl_xor_sync(0xffffffffu, c1, 1);
                float o2 = __shfl_xor_sync(0xffffffffu, c2, 1);
                float o3 = __shfl_xor_sync(0xffffffffu, c3, 1);
                if ((qcol & 1) == 0) {
                    const int j = (nb >> 2) + (qcol >> 1);
                    if (j < H_DIM) {
                        const float4 zv0 = *(const float4*)(zx + (size_t)r0 * H4 + 4 * j);
                        const float4 zv1 = *(const float4*)(zx + (size_t)(r0 + 8) * H4 + 4 * j);
#pragma unroll
                        for (int h = 0; h < 2; ++h) {
                            const int r = r0 + h * 8;
                            const float4 zv = h ? zv1 : zv0;
                            float zi = (h ? c2 : c0) + zv.x;
                            float zf = (h ? c3 : c1) + zv.y;
                            float zo = (h ? o2 : o0) + zv.z;
                            float zu = (h ? o3 : o1) + zv.w;
                            float iv = sigmoidf_(zi), fv = sigmoidf_(zf), ov = sigmoidf_(zo);
                            float uv = tanhf(zu);
                            size_t o = (size_t)r * H_DIM + j;
                            float c = fv * cprev[o] + iv * uv;
                            outh[o] = ov * tanhf(c);
                            outc[o] = c;
                        }
                    }
                }
            }
        }
    }
}

// ------------------------------------------------------------------
// launch
// ------------------------------------------------------------------
extern "C" void kernel_launch(void* const* d_in, const int* in_sizes, int n_in,
                              void* d_out, int out_size) {
    const float* inputs = (const float*)d_in[0];
    const float* c_prev = (const float*)d_in[1];
    const float* h_prev = (const float*)d_in[2];
    const float* wx     = (const float*)d_in[3];
    const float* wh     = (const float*)d_in[4];
    const float* wmx    = (const float*)d_in[5];
    const float* wmh    = (const float*)d_in[6];
    const float* bvec   = (const float*)d_in[7];
    const float* gx     = (const float*)d_in[8];
    const float* gh     = (const float*)d_in[9];
    const float* gmx    = (const float*)d_in[10];
    const float* gmh    = (const float*)d_in[11];

    float* out_h = (float*)d_out;
    float* out_c = out_h + (size_t)B_DIM * H_DIM;

    float *sx, *sh, *smx, *smh, *xm, *zx;
    unsigned short *mhi, *mlo, *hhi, *hlo, *wh16, *wmhhi, *wmhlo;
    cudaGetSymbolAddress((void**)&sx,   g_sx);
    cudaGetSymbolAddress((void**)&sh,   g_sh);
    cudaGetSymbolAddress((void**)&smx,  g_smx);
    cudaGetSymbolAddress((void**)&smh,  g_smh);
    cudaGetSymbolAddress((void**)&xm,   g_xm);
    cudaGetSymbolAddress((void**)&zx,   g_zx);
    cudaGetSymbolAddress((void**)&mhi,  g_mhi);
    cudaGetSymbolAddress((void**)&mlo,  g_mlo);
    cudaGetSymbolAddress((void**)&hhi,  g_hhi);
    cudaGetSymbolAddress((void**)&hlo,  g_hlo);
    cudaGetSymbolAddress((void**)&wh16, g_wh16);
    cudaGetSymbolAddress((void**)&wmhhi, g_wmhhi);
    cudaGetSymbolAddress((void**)&wmhlo, g_wmhlo);

    cudaFuncSetAttribute(tc_gemm_kernel<0>, cudaFuncAttributeMaxDynamicSharedMemorySize, 4 * TILE_B * 2);
    cudaFuncSetAttribute(tc_gemm_kernel<1>, cudaFuncAttributeMaxDynamicSharedMemorySize, 3 * TILE_B * 2);

    // 1) per-column scales (parallel reduction)
    colnorm_kernel<<<(H4 + 31) / 32, 256>>>(wx, gx, sx, DIN, H4);
    colnorm_kernel<<<(H4 + 31) / 32, 256>>>(wh, gh, sh, H_DIM, H4);
    colnorm_kernel<<<(H_DIM + 31) / 32, 256>>>(wmx, gmx, smx, DIN, H_DIM);
    colnorm_kernel<<<(H_DIM + 31) / 32, 256>>>(wmh, gmh, smh, H_DIM, H_DIM);

    // 2) K=10 input GEMMs
    input_gemm_plain<<<(int)(((long long)B_DIM * H_DIM + 255) / 256), 256>>>(inputs, wmx, smx, xm);
    input_gemm_gates<<<(int)(((long long)B_DIM * H4 + 255) / 256), 256>>>(inputs, wx, sx, bvec, zx);

    // 3) operand conversions
    split_pad_kernel<<<(int)(((long long)B_DIM * KP + 255) / 256), 256>>>(h_prev, hhi, hlo, H_DIM, (long long)B_DIM * KP);
    {
        dim3 blk(32, 32);
        dim3 gm((H_DIM + 31) / 32, KP / 32);
        transp_split_kernel<0, 1><<<gm, blk>>>(wmh, smh, wmhhi, wmhlo, H_DIM, H_DIM);
        dim3 gz((H4 + 31) / 32, KP / 32);
        transp_split_kernel<1, 0><<<gz, blk>>>(wh, sh, wh16, nullptr, H_DIM, H4);
    }

    // 4) GEMM-m (3-term): m = xm * (h_prev @ wmh_n) -> fp16 split
    {
        dim3 grid(NP_M / 128, B_DIM / 128);
        tc_gemm_kernel<0><<<grid, 256, 4 * TILE_B * 2>>>(hhi, hlo, wmhhi, wmhlo,
                                                 xm, nullptr, nullptr, nullptr, nullptr, mhi, mlo);
    }
    // 5) GEMM-z (2-term) fused gates -> (h, c)
    {
        dim3 grid(NP_Z / 128, B_DIM / 128);
        tc_gemm_kernel<1><<<grid, 256, 3 * TILE_B * 2>>>(mhi, mlo, wh16, nullptr,
                                                 nullptr, zx, c_prev, out_h, out_c, nullptr, nullptr);
    }
    (void)in_sizes; (void)n_in; (void)out_size;
}

// round 7
// speedup vs baseline: 4.1488x; 1.3535x over previous
#include <cuda_runtime.h>
#include <cuda_fp16.h>
#include <cstdint>
#include <math.h>

#define B_DIM 8192
#define DIN   10
#define H_DIM 1900
#define H4    7600
#define KP    1920          // padded K (both GEMMs)
#define NP_Z  7680          // padded N for gate GEMM
#define NP_M  1920          // padded N for m GEMM
#define KT    32            // k-tile
#define NKT   60            // k-tiles of 32

// ------------------------------------------------------------------
// static device scratch (zero-initialized at load; pads never written stay 0)
// ------------------------------------------------------------------
__device__ float g_sx [H4];
__device__ float g_sh [H4];
__device__ float g_smx[H_DIM];
__device__ float g_smh[H_DIM];
__device__ float g_xm [(size_t)B_DIM * H_DIM];   // inputs @ wmx_n
__device__ float g_zx [(size_t)B_DIM * H4];      // inputs @ wx_n + b (gate-interleaved n=j*4+g)
__device__ unsigned short g_m16 [(size_t)B_DIM * KP];   // m, single fp16
__device__ unsigned short g_hhi [(size_t)B_DIM * KP];   // h_prev split hi
__device__ unsigned short g_hlo [(size_t)B_DIM * KP];   // h_prev split lo
__device__ unsigned short g_wh16[(size_t)NP_Z * KP];    // wh_n transposed+interleaved fp16
__device__ unsigned short g_wmh16[(size_t)NP_M * KP];   // wmh_n transposed fp16

// ------------------------------------------------------------------
__device__ __forceinline__ uint32_t smem_u32(const void* p) {
    uint32_t a;
    asm("{ .reg .u64 t; cvta.to.shared.u64 t, %1; cvt.u32.u64 %0, t; }" : "=r"(a) : "l"(p));
    return a;
}
__device__ __forceinline__ void ldsm_x4(uint32_t (&r)[4], uint32_t addr) {
    asm volatile("ldmatrix.sync.aligned.m8n8.x4.shared.b16 {%0,%1,%2,%3}, [%4];"
        : "=r"(r[0]), "=r"(r[1]), "=r"(r[2]), "=r"(r[3]) : "r"(addr));
}
__device__ __forceinline__ void mma16816(float (&d)[4], const uint32_t (&a)[4],
                                         uint32_t b0, uint32_t b1) {
    asm volatile("mma.sync.aligned.m16n8k16.row.col.f32.f16.f16.f32 "
        "{%0,%1,%2,%3}, {%4,%5,%6,%7}, {%8,%9}, {%0,%1,%2,%3};"
        : "+f"(d[0]), "+f"(d[1]), "+f"(d[2]), "+f"(d[3])
        : "r"(a[0]), "r"(a[1]), "r"(a[2]), "r"(a[3]), "r"(b0), "r"(b1));
}
__device__ __forceinline__ float sigmoidf_(float x) { return 1.0f / (1.0f + __expf(-x)); }
__device__ __forceinline__ unsigned short f2h_bits(float v) {
    return __half_as_ushort(__float2half(v));
}

// ------------------------------------------------------------------
// per-column l2 scale, parallel over rows: block = 32 cols x 8 row-lanes
// ------------------------------------------------------------------
__global__ void colnorm_kernel(const float* __restrict__ w, const float* __restrict__ g,
                               float* __restrict__ s, int rows, int cols) {
    __shared__ float red[8][33];
    const int jl = threadIdx.x & 31, rl = threadIdx.x >> 5;
    const int j = blockIdx.x * 32 + jl;
    float acc = 0.f;
    if (j < cols) {
        for (int i = rl; i < rows; i += 8) {
            float a = w[(size_t)i * cols + j];
            acc += a * a;
        }
    }
    red[rl][jl] = acc;
    __syncthreads();
    if (rl == 0 && j < cols) {
        float t = 0.f;
#pragma unroll
        for (int r = 0; r < 8; ++r) t += red[r][jl];
        s[j] = g[j] * rsqrtf(fmaxf(t, 1e-12f));
    }
}

// ------------------------------------------------------------------
// K=10 input GEMMs
// ------------------------------------------------------------------
__global__ void input_gemm_plain(const float* __restrict__ x, const float* __restrict__ w,
                                 const float* __restrict__ s, float* __restrict__ out) {
    long long idx = (long long)blockIdx.x * blockDim.x + threadIdx.x;
    if (idx >= (long long)B_DIM * H_DIM) return;
    int b = (int)(idx / H_DIM), j = (int)(idx - (long long)b * H_DIM);
    const float* xr = x + b * DIN;
    float acc = 0.f;
#pragma unroll
    for (int k = 0; k < DIN; ++k) acc += xr[k] * w[(size_t)k * H_DIM + j];
    out[idx] = acc * s[j];
}
// gate-interleaved zx: out[b][j*4+g] = (x @ wx_n)[b][g*1900+j] + bias
__global__ void input_gemm_gates(const float* __restrict__ x, const float* __restrict__ w,
                                 const float* __restrict__ s, const float* __restrict__ bias,
                                 float* __restrict__ out) {
    long long idx = (long long)blockIdx.x * blockDim.x + threadIdx.x;
    if (idx >= (long long)B_DIM * H4) return;
    int b = (int)(idx / H4), n = (int)(idx - (long long)b * H4);
    int j = n >> 2, g = n & 3;
    int col = g * H_DIM + j;
    const float* xr = x + b * DIN;
    float acc = 0.f;
#pragma unroll
    for (int k = 0; k < DIN; ++k) acc += xr[k] * w[(size_t)k * H4 + col];
    out[idx] = acc * s[col] + bias[col];
}

// ------------------------------------------------------------------
// fp32 -> fp16 hi/lo split with K-padding (row-major [rows, KP])
// ------------------------------------------------------------------
__global__ void split_pad_kernel(const float* __restrict__ x, unsigned short* __restrict__ hi,
                                 unsigned short* __restrict__ lo, int cols, long long total) {
    long long idx = (long long)blockIdx.x * blockDim.x + threadIdx.x;
    if (idx >= total) return;
    int c = (int)(idx % KP);
    long long r = idx / KP;
    float v = (c < cols) ? x[r * cols + c] : 0.f;
    __half h = __float2half(v);
    hi[idx] = __half_as_ushort(h);
    lo[idx] = f2h_bits(v - __half2float(h));
}

// ------------------------------------------------------------------
// transpose + scale -> single fp16:  o[n(c)][k] = w[k][c] * s[c]
// ILV=1: n = (c%1900)*4 + c/1900 (gate interleave), else n = c
// ------------------------------------------------------------------
template<int ILV>
__global__ void transp_h16_kernel(const float* __restrict__ w, const float* __restrict__ s,
                                  unsigned short* __restrict__ o16, int K, int NC) {
    __shared__ float tile[32][33];
    int c0 = blockIdx.x * 32, k0 = blockIdx.y * 32;
    int tx = threadIdx.x, ty = threadIdx.y;
    int c = c0 + tx, k = k0 + ty;
    float v = 0.f;
    if (c < NC && k < K) v = w[(size_t)k * NC + c] * s[c];
    tile[ty][tx] = v;
    __syncthreads();
    c = c0 + ty; k = k0 + tx;
    if (c < NC) {
        float val = tile[tx][ty];
        int n = ILV ? ((c % H_DIM) * 4 + c / H_DIM) : c;
        o16[(size_t)n * KP + k] = f2h_bits(val);
    }
}

// ------------------------------------------------------------------
// mma.sync fp16 GEMM, 128x128x32 tile, 8 warps (32x64 each).
// MODE 0 (2-term): D = (Ahi+Alo)@B : hprev@wmh_n ; m = D*xm -> single fp16
// MODE 1 (1-term): D = A@B : m@wh_n ; fused gate epilogue -> (h,c)
// ------------------------------------------------------------------
#define TILE_B  8192               // one operand tile: 128 x 32 x 2B

template<int MODE>
__global__ __launch_bounds__(256, 2)
void tc_gemm_kernel(const unsigned short* __restrict__ Ahi_, const unsigned short* __restrict__ Alo_,
                    const unsigned short* __restrict__ B_,
                    const float* __restrict__ xm, const float* __restrict__ zx,
                    const float* __restrict__ cprev,
                    float* __restrict__ outh, float* __restrict__ outc,
                    unsigned short* __restrict__ mout) {
    constexpr int NOPS = (MODE == 0) ? 3 : 2;   // #tiles per stage
    constexpr int NA   = NOPS - 1;              // #A tiles
    constexpr int STAGE_B = NOPS * TILE_B;
    extern __shared__ char smem[];
    const uint32_t sb = smem_u32(smem);
    const int tid = threadIdx.x;
    const int wid = tid >> 5, lane = tid & 31;
    const int wm = wid & 3, wn = wid >> 2;          // warp tile: rows wm*32, cols wn*64
    const int lrow = lane & 15, lseg = lane >> 4;
    const int m0 = blockIdx.y * 128, n0 = blockIdx.x * 128;

    const unsigned short* srcs[3] = {Ahi_, (NA == 2) ? Alo_ : B_, B_};

    // row of KT=32 fp16 = 64 bytes = 4 x 16B units; swizzle u ^ (row&3)
    auto load_tile = [&](int st, int kt) {
        uint32_t base = sb + st * STAGE_B;
#pragma unroll
        for (int T = 0; T < NOPS; ++T) {
            const int rb = (T < NA) ? m0 : n0;
            const unsigned short* src = srcs[T];
#pragma unroll
            for (int i = 0; i < 2; ++i) {
                int cid = tid + i * 256;
                int row = cid >> 2, u = cid & 3;
                uint32_t so = base + T * TILE_B + row * 64 + ((u ^ (row & 3)) << 4);
                const void* gp = (const void*)(src + (size_t)(rb + row) * KP + kt * KT + u * 8);
                asm volatile("cp.async.cg.shared.global [%0], [%1], 16;" :: "r"(so), "l"(gp));
            }
        }
        asm volatile("cp.async.commit_group;" ::: "memory");
    };

    float acc[2][8][4];
#pragma unroll
    for (int a = 0; a < 2; ++a)
#pragma unroll
        for (int b = 0; b < 8; ++b)
#pragma unroll
            for (int c = 0; c < 4; ++c) acc[a][b][c] = 0.f;

    load_tile(0, 0);

    for (int kt = 0; kt < NKT; ++kt) {
        const int cur = kt & 1;
        if (kt + 1 < NKT) {
            load_tile(cur ^ 1, kt + 1);
            asm volatile("cp.async.wait_group 1;" ::: "memory");
        } else {
            asm volatile("cp.async.wait_group 0;" ::: "memory");
        }
        __syncthreads();

        const uint32_t stb = sb + cur * STAGE_B;
#pragma unroll
        for (int ks = 0; ks < 2; ++ks) {
            uint32_t ah[2][4], al[2][4], bb[4][4];
#pragma unroll
            for (int mt = 0; mt < 2; ++mt) {
                int row = wm * 32 + mt * 16 + lrow;
                uint32_t sw = (uint32_t)(((ks * 2 + lseg) ^ (row & 3)) << 4) + (uint32_t)row * 64;
                ldsm_x4(ah[mt], stb + 0 * TILE_B + sw);
                if (MODE == 0) ldsm_x4(al[mt], stb + 1 * TILE_B + sw);
            }
#pragma unroll
            for (int q = 0; q < 4; ++q) {
                int row = wn * 64 + q * 16 + lrow;
                uint32_t sw = (uint32_t)(((ks * 2 + lseg) ^ (row & 3)) << 4) + (uint32_t)row * 64;
                ldsm_x4(bb[q], stb + NA * TILE_B + sw);
            }
            // pass 1: Ahi * B
#pragma unroll
            for (int mt = 0; mt < 2; ++mt)
#pragma unroll
                for (int q = 0; q < 4; ++q) {
                    mma16816(acc[mt][2 * q + 0], ah[mt], bb[q][0], bb[q][2]);
                    mma16816(acc[mt][2 * q + 1], ah[mt], bb[q][1], bb[q][3]);
                }
            if (MODE == 0) {
                // pass 2: Alo * B
#pragma unroll
                for (int mt = 0; mt < 2; ++mt)
#pragma unroll
                    for (int q = 0; q < 4; ++q) {
                        mma16816(acc[mt][2 * q + 0], al[mt], bb[q][0], bb[q][2]);
                        mma16816(acc[mt][2 * q + 1], al[mt], bb[q][1], bb[q][3]);
                    }
            }
        }
        __syncthreads();
    }

    // ---------------- epilogue ----------------
    // fragment: c0,c1 at (row = l/4, n = 2*(l%4)+{0,1}); c2,c3 at row+8
    const int qrow = lane >> 2, qcol = lane & 3;
#pragma unroll
    for (int mt = 0; mt < 2; ++mt) {
        const int r0 = m0 + wm * 32 + mt * 16 + qrow;   // and r0+8
#pragma unroll
        for (int nt = 0; nt < 8; ++nt) {
            const int nb = n0 + wn * 64 + nt * 8;
            float c0 = acc[mt][nt][0], c1 = acc[mt][nt][1];
            float c2 = acc[mt][nt][2], c3 = acc[mt][nt][3];
            if (MODE == 0) {
                const int n = nb + 2 * qcol;
#pragma unroll
                for (int h = 0; h < 2; ++h) {
                    const int r = r0 + h * 8;
                    float v0 = (h ? c2 : c0), v1 = (h ? c3 : c1);
                    float m0v = (n + 0 < H_DIM) ? v0 * xm[(size_t)r * H_DIM + n + 0] : 0.f;
                    float m1v = (n + 1 < H_DIM) ? v1 * xm[(size_t)r * H_DIM + n + 1] : 0.f;
                    uint32_t hp = ((uint32_t)f2h_bits(m1v) << 16) | f2h_bits(m0v);
                    *(uint32_t*)(mout + (size_t)r * KP + n) = hp;
                }
            } else {
                // exchange within lane pair: even lane holds (zi,zf), odd holds (zo,zu)
                float o0 = __shfl_xor_sync(0xffffffffu, c0, 1);
                float o1 = __shfl_xor_sync(0xffffffffu, c1, 1);
                float o2 = __shfl_xor_sync(0xffffffffu, c2, 1);
                float o3 = __shfl_xor_sync(0xffffffffu, c3, 1);
                if ((qcol & 1) == 0) {
                    const int j = (nb >> 2) + (qcol >> 1);
                    if (j < H_DIM) {
                        const float4 zv0 = *(const float4*)(zx + (size_t)r0 * H4 + 4 * j);
                        const float4 zv1 = *(const float4*)(zx + (size_t)(r0 + 8) * H4 + 4 * j);
#pragma unroll
                        for (int h = 0; h < 2; ++h) {
                            const int r = r0 + h * 8;
                            const float4 zv = h ? zv1 : zv0;
                            float zi = (h ? c2 : c0) + zv.x;
                            float zf = (h ? c3 : c1) + zv.y;
                            float zo = (h ? o2 : o0) + zv.z;
                            float zu = (h ? o3 : o1) + zv.w;
                            float iv = sigmoidf_(zi), fv = sigmoidf_(zf), ov = sigmoidf_(zo);
                            float uv = tanhf(zu);
                            size_t o = (size_t)r * H_DIM + j;
                            float c = fv * cprev[o] + iv * uv;
                            outh[o] = ov * tanhf(c);
                            outc[o] = c;
                        }
                    }
                }
            }
        }
    }
}

// ------------------------------------------------------------------
// launch
// ------------------------------------------------------------------
extern "C" void kernel_launch(void* const* d_in, const int* in_sizes, int n_in,
                              void* d_out, int out_size) {
    const float* inputs = (const float*)d_in[0];
    const float* c_prev = (const float*)d_in[1];
    const float* h_prev = (const float*)d_in[2];
    const float* wx     = (const float*)d_in[3];
    const float* wh     = (const float*)d_in[4];
    const float* wmx    = (const float*)d_in[5];
    const float* wmh    = (const float*)d_in[6];
    const float* bvec   = (const float*)d_in[7];
    const float* gx     = (const float*)d_in[8];
    const float* gh     = (const float*)d_in[9];
    const float* gmx    = (const float*)d_in[10];
    const float* gmh    = (const float*)d_in[11];

    float* out_h = (float*)d_out;
    float* out_c = out_h + (size_t)B_DIM * H_DIM;

    float *sx, *sh, *smx, *smh, *xm, *zx;
    unsigned short *m16, *hhi, *hlo, *wh16, *wmh16;
    cudaGetSymbolAddress((void**)&sx,    g_sx);
    cudaGetSymbolAddress((void**)&sh,    g_sh);
    cudaGetSymbolAddress((void**)&smx,   g_smx);
    cudaGetSymbolAddress((void**)&smh,   g_smh);
    cudaGetSymbolAddress((void**)&xm,    g_xm);
    cudaGetSymbolAddress((void**)&zx,    g_zx);
    cudaGetSymbolAddress((void**)&m16,   g_m16);
    cudaGetSymbolAddress((void**)&hhi,   g_hhi);
    cudaGetSymbolAddress((void**)&hlo,   g_hlo);
    cudaGetSymbolAddress((void**)&wh16,  g_wh16);
    cudaGetSymbolAddress((void**)&wmh16, g_wmh16);

    cudaFuncSetAttribute(tc_gemm_kernel<0>, cudaFuncAttributeMaxDynamicSharedMemorySize, 2 * 3 * TILE_B);
    cudaFuncSetAttribute(tc_gemm_kernel<1>, cudaFuncAttributeMaxDynamicSharedMemorySize, 2 * 2 * TILE_B);

    // 1) per-column scales (parallel reduction)
    colnorm_kernel<<<(H4 + 31) / 32, 256>>>(wx, gx, sx, DIN, H4);
    colnorm_kernel<<<(H4 + 31) / 32, 256>>>(wh, gh, sh, H_DIM, H4);
    colnorm_kernel<<<(H_DIM + 31) / 32, 256>>>(wmx, gmx, smx, DIN, H_DIM);
    colnorm_kernel<<<(H_DIM + 31) / 32, 256>>>(wmh, gmh, smh, H_DIM, H_DIM);

    // 2) K=10 input GEMMs
    input_gemm_plain<<<(int)(((long long)B_DIM * H_DIM + 255) / 256), 256>>>(inputs, wmx, smx, xm);
    input_gemm_gates<<<(int)(((long long)B_DIM * H4 + 255) / 256), 256>>>(inputs, wx, sx, bvec, zx);

    // 3) operand conversions
    split_pad_kernel<<<(int)(((long long)B_DIM * KP + 255) / 256), 256>>>(h_prev, hhi, hlo, H_DIM, (long long)B_DIM * KP);
    {
        dim3 blk(32, 32);
        dim3 gm((H_DIM + 31) / 32, KP / 32);
        transp_h16_kernel<0><<<gm, blk>>>(wmh, smh, wmh16, H_DIM, H_DIM);
        dim3 gz((H4 + 31) / 32, KP / 32);
        transp_h16_kernel<1><<<gz, blk>>>(wh, sh, wh16, H_DIM, H4);
    }

    // 4) GEMM-m (2-term): m = xm * (h_prev @ wmh_n) -> single fp16
    {
        dim3 grid(NP_M / 128, B_DIM / 128);
        tc_gemm_kernel<0><<<grid, 256, 2 * 3 * TILE_B>>>(hhi, hlo, wmh16,
                                                 xm, nullptr, nullptr, nullptr, nullptr, m16);
    }
    // 5) GEMM-z (1-term) fused gates -> (h, c)
    {
        dim3 grid(NP_Z / 128, B_DIM / 128);
        tc_gemm_kernel<1><<<grid, 256, 2 * 2 * TILE_B>>>(m16, nullptr, wh16,
                                                 nullptr, zx, c_prev, out_h, out_c, nullptr);
    }
    (void)in_sizes; (void)n_in; (void)out_size;
}